// round 16
// baseline (speedup 1.0000x reference)
#include <cuda_runtime.h>
#include <cuda_bf16.h>
#include <math.h>
#include <stdint.h>

#define S_ 512
#define K_ 512
#define Q_ 64
#define D_ 256
#define H_ 8
#define DH_ 32
#define EPSV 1e-5f

// ---------------- scratch ----------------
__device__ float    g_Qp [(size_t)S_ * Q_ * D_];
__device__ float    g_O  [(size_t)S_ * Q_ * D_];
__device__ __nv_bfloat16 g_Whi[4][D_ * D_];             // 0=k,1=v,2=q,3=l
__device__ __nv_bfloat16 g_Wlo[4][D_ * D_];
__device__ uint32_t g_AQhi[(size_t)S_ * Q_ * (D_ / 2)];
__device__ uint32_t g_AQlo[(size_t)S_ * Q_ * (D_ / 2)];
__device__ uint32_t g_Khi[(size_t)S_ * K_ * (D_ / 2)];
__device__ uint32_t g_Vhi[(size_t)S_ * K_ * (D_ / 2)];
__device__ uint32_t g_Qhi[(size_t)S_ * Q_ * (D_ / 2)];  // bf16(Qp/16)

// ---------------- helpers ----------------
__device__ __forceinline__ uint32_t smem_u32(const void* p) {
    uint32_t a;
    asm("{ .reg .u64 t; cvta.to.shared.u64 t, %1; cvt.u32.u64 %0, t; }" : "=r"(a) : "l"(p));
    return a;
}
__device__ __forceinline__ void split2(float a, float b, uint32_t& hi, uint32_t& lo) {
    __nv_bfloat16 ah = __float2bfloat16_rn(a);
    __nv_bfloat16 bh = __float2bfloat16_rn(b);
    __nv_bfloat16 al = __float2bfloat16_rn(a - __bfloat162float(ah));
    __nv_bfloat16 bl = __float2bfloat16_rn(b - __bfloat162float(bh));
    hi = (uint32_t)*(uint16_t*)&ah | ((uint32_t)*(uint16_t*)&bh << 16);
    lo = (uint32_t)*(uint16_t*)&al | ((uint32_t)*(uint16_t*)&bl << 16);
}
__device__ __forceinline__ uint32_t pack_bf16(float a, float b) {
    __nv_bfloat162 t = __floats2bfloat162_rn(a, b);
    return *(uint32_t*)&t;
}
__device__ __forceinline__ void mma_bf16(float* c, const uint32_t* a, uint32_t b0, uint32_t b1) {
    asm volatile(
        "mma.sync.aligned.m16n8k16.row.col.f32.bf16.bf16.f32 "
        "{%0,%1,%2,%3}, {%4,%5,%6,%7}, {%8,%9}, {%0,%1,%2,%3};"
        : "+f"(c[0]), "+f"(c[1]), "+f"(c[2]), "+f"(c[3])
        : "r"(a[0]), "r"(a[1]), "r"(a[2]), "r"(a[3]), "r"(b0), "r"(b1));
}
__device__ __forceinline__ void ldsm4(uint32_t* r, uint32_t addr) {
    asm volatile("ldmatrix.sync.aligned.m8n8.x4.shared.b16 {%0,%1,%2,%3}, [%4];"
                 : "=r"(r[0]), "=r"(r[1]), "=r"(r[2]), "=r"(r[3]) : "r"(addr));
}
__device__ __forceinline__ void ldsm4t(uint32_t* r, uint32_t addr) {
    asm volatile("ldmatrix.sync.aligned.m8n8.x4.trans.shared.b16 {%0,%1,%2,%3}, [%4];"
                 : "=r"(r[0]), "=r"(r[1]), "=r"(r[2]), "=r"(r[3]) : "r"(addr));
}
#define CP16(dst, src) asm volatile("cp.async.cg.shared.global [%0], [%1], 16;" :: "r"(dst), "l"(src) : "memory")
#define CP_COMMIT()    asm volatile("cp.async.commit_group;" ::: "memory")
#define CP_WAIT0()     asm volatile("cp.async.wait_group 0;" ::: "memory")
#define CP_WAIT1()     asm volatile("cp.async.wait_group 1;" ::: "memory")
#define CP_WAIT2()     asm volatile("cp.async.wait_group 2;" ::: "memory")

// ---------------- kernel 0: merged prep (wconv + qprep) ----------------
__global__ void prep_kernel(const float* __restrict__ Wk, const float* __restrict__ Wv,
                            const float* __restrict__ Wq, const float* __restrict__ Wl,
                            const int* __restrict__ add_ids,
                            const int* __restrict__ target_ids,
                            const float* __restrict__ x) {
    int bx = blockIdx.x;
    if (bx < 256) {
        int i = bx * 256 + threadIdx.x;
        const float* src[4] = {Wk, Wv, Wq, Wl};
        #pragma unroll
        for (int w = 0; w < 4; w++) {
            float v = src[w][i];
            __nv_bfloat16 h = __float2bfloat16_rn(v);
            __nv_bfloat16 l = __float2bfloat16_rn(v - __bfloat162float(h));
            g_Whi[w][i] = h;
            g_Wlo[w][i] = l;
        }
    } else {
        int qi = (bx - 256) * 8 + (threadIdx.x >> 5);
        int lane = threadIdx.x & 31;
        int s = qi >> 6;
        int xrow = target_ids[s * K_ + add_ids[qi]];
        const float4* sp = (const float4*)(x + (size_t)xrow * D_ + lane * 8);
        float4 v0 = sp[0], v1 = sp[1];
        uint4 h, l;
        split2(v0.x, v0.y, h.x, l.x);
        split2(v0.z, v0.w, h.y, l.y);
        split2(v1.x, v1.y, h.z, l.z);
        split2(v1.z, v1.w, h.w, l.w);
        *(uint4*)(g_AQhi + (size_t)qi * 128 + lane * 4) = h;
        *(uint4*)(g_AQlo + (size_t)qi * 128 + lane * 4) = l;
    }
}

// ---------------- kernel 1: merged projection GEMM ----------------
#define KV_AF32 0u
#define KV_ABF  16384u
#define KV_B    26624u
#define KV_STAGE 47104u
#define QSA_HI 0u
#define QSA_LO 10240u
#define QSB_HI 20480u
#define QSB_LO 40960u
#define QSTAGE 61440u
#define PROJ_SMEM (3 * 61440)

__global__ __launch_bounds__(512, 1) void gemm_all_kernel(
    const float* __restrict__ x, const int* __restrict__ target_ids,
    const float* __restrict__ bk, const float* __restrict__ bv,
    const float* __restrict__ bq, float* __restrict__ d_out)
{
    extern __shared__ char smem[];
    uint32_t sb = smem_u32(smem);
    int tid = threadIdx.x, wid = tid >> 5, lane = tid & 31;
    int grp = lane >> 2, qid = lane & 3;
    int ln15 = lane & 15, l16 = (lane >> 4) * 8;
    int mw = (wid & 3) * 32, nw = (wid >> 2) * 64;
    int bx = blockIdx.x;

    if (bx < 4096) {
        int sel = bx & 1;
        int m0 = (bx >> 1) * 128;
        const float* bias = sel ? bv : bk;

        int arow = tid >> 3, apart = tid & 7;
        int rid0 = target_ids[m0 + arow];
        int rid1 = target_ids[m0 + 64 + arow];
        const float* ax0 = x + (size_t)rid0 * D_ + apart * 4;
        const float* ax1 = x + (size_t)rid1 * D_ + apart * 4;
        uint32_t adst0 = sb + KV_AF32 + (uint32_t)tid * 16;
        uint32_t adst1 = sb + KV_AF32 + (uint32_t)(tid + 512) * 16;

        int rb_row = tid >> 1, rb_h = tid & 1;
        const uint32_t* bH = (const uint32_t*)g_Whi[sel] + (size_t)rb_row * 128 + rb_h * 8;
        uint32_t bdst = sb + KV_B + rb_row * 80 + rb_h * 32;

        int crow = tid >> 2, cq = tid & 3;
        bool wr_out = (sel == 0);

        #define KV_LOAD(slot, kc) do { \
            uint32_t so = (uint32_t)(slot) * KV_STAGE; \
            CP16(adst0 + so, ax0 + (kc) * 32); \
            CP16(adst1 + so, ax1 + (kc) * 32); \
            CP16(bdst + so, bH + (kc) * 16); \
            CP16(bdst + so + 16, bH + (kc) * 16 + 4); \
            CP_COMMIT(); \
        } while (0)

        float c[2][8][4];
        #pragma unroll
        for (int mt = 0; mt < 2; mt++)
            #pragma unroll
            for (int nt = 0; nt < 8; nt++)
                #pragma unroll
                for (int i = 0; i < 4; i++) c[mt][nt][i] = 0.f;

        KV_LOAD(0, 0);
        KV_LOAD(1, 1);
        KV_LOAD(2, 2);

        for (int kc = 0; kc < 8; kc++) {
            if (kc < 6) { CP_WAIT2(); } else if (kc == 6) { CP_WAIT1(); } else { CP_WAIT0(); }
            __syncthreads();
            uint32_t so = (uint32_t)(kc % 3) * KV_STAGE;
            char* stgc = smem + so;

            {
                const float4* fsrc = (const float4*)(stgc + KV_AF32 + crow * 128 + cq * 32);
                float4 a0 = fsrc[0], a1 = fsrc[1];
                uint4 hv;
                hv.x = pack_bf16(a0.x, a0.y);
                hv.y = pack_bf16(a0.z, a0.w);
                hv.z = pack_bf16(a1.x, a1.y);
                hv.w = pack_bf16(a1.z, a1.w);
                *(uint4*)(stgc + KV_ABF + crow * 80 + cq * 16) = hv;
                if (wr_out) {
                    float4* op = (float4*)(d_out + (size_t)(m0 + crow) * D_ + kc * 32 + cq * 8);
                    op[0] = a0; op[1] = a1;
                }
            }
            __syncthreads();

            uint32_t stg = sb + so;
            #pragma unroll
            for (int ks = 0; ks < 2; ks++) {
                int k0 = ks * 16;
                uint32_t ah[2][4];
                #pragma unroll
                for (int mt = 0; mt < 2; mt++) {
                    uint32_t ra = stg + KV_ABF + (mw + mt * 16 + ln15) * 80 + (k0 + l16) * 2;
                    ldsm4(ah[mt], ra);
                }
                #pragma unroll
                for (int nt = 0; nt < 4; nt++) {
                    uint32_t rb = stg + KV_B + (nw + nt * 16 + ln15) * 80 + (k0 + l16) * 2;
                    uint32_t bh[4];
                    ldsm4(bh, rb);
                    mma_bf16(c[0][2 * nt],     ah[0], bh[0], bh[2]);
                    mma_bf16(c[1][2 * nt],     ah[1], bh[0], bh[2]);
                    mma_bf16(c[0][2 * nt + 1], ah[0], bh[1], bh[3]);
                    mma_bf16(c[1][2 * nt + 1], ah[1], bh[1], bh[3]);
                }
            }
            __syncthreads();
            if (kc + 3 < 8) KV_LOAD(kc % 3, kc + 3);
        }

        uint32_t* outp = sel ? g_Vhi : g_Khi;
        #pragma unroll
        for (int mt = 0; mt < 2; mt++) {
            int m = m0 + mw + mt * 16 + grp;
            #pragma unroll
            for (int nt = 0; nt < 8; nt++) {
                int n = nw + nt * 8 + qid * 2;
                float b0 = bias[n], b1 = bias[n + 1];
                outp[(size_t)m * 128 + n / 2]       = pack_bf16(c[mt][nt][0] + b0, c[mt][nt][1] + b1);
                outp[(size_t)(m + 8) * 128 + n / 2] = pack_bf16(c[mt][nt][2] + b0, c[mt][nt][3] + b1);
            }
        }
        #undef KV_LOAD
    } else {
        int m0 = (bx - 4096) * 128;
        const float* bias = bq;

        int ra_row = tid >> 2, ra_sg = tid & 3;
        int rb_row = tid >> 1, rb_h = (tid & 1);
        const uint32_t* aH = g_AQhi + (size_t)(m0 + ra_row) * 128 + ra_sg * 4;
        const uint32_t* aL = g_AQlo + (size_t)(m0 + ra_row) * 128 + ra_sg * 4;
        const uint32_t* bH = (const uint32_t*)g_Whi[2] + (size_t)rb_row * 128 + rb_h * 8;
        const uint32_t* bL = (const uint32_t*)g_Wlo[2] + (size_t)rb_row * 128 + rb_h * 8;
        uint32_t adst = sb + ra_row * 80 + ra_sg * 16;
        uint32_t bdst = sb + rb_row * 80 + rb_h * 32;

        #define Q_LOAD(slot, kc) do { \
            uint32_t so = (uint32_t)(slot) * QSTAGE; \
            int ko = (kc) * 16; \
            CP16(adst + so + QSA_HI, aH + ko); \
            CP16(adst + so + QSA_LO, aL + ko); \
            CP16(bdst + so + QSB_HI, bH + ko); \
            CP16(bdst + so + QSB_HI + 16, bH + ko + 4); \
            CP16(bdst + so + QSB_LO, bL + ko); \
            CP16(bdst + so + QSB_LO + 16, bL + ko + 4); \
            CP_COMMIT(); \
        } while (0)

        float c[2][8][4];
        #pragma unroll
        for (int mt = 0; mt < 2; mt++)
            #pragma unroll
            for (int nt = 0; nt < 8; nt++)
                #pragma unroll
                for (int i = 0; i < 4; i++) c[mt][nt][i] = 0.f;

        Q_LOAD(0, 0);
        Q_LOAD(1, 1);
        Q_LOAD(2, 2);

        for (int kc = 0; kc < 8; kc++) {
            if (kc < 6) { CP_WAIT2(); } else if (kc == 6) { CP_WAIT1(); } else { CP_WAIT0(); }
            __syncthreads();
            uint32_t stg = sb + (uint32_t)(kc % 3) * QSTAGE;

            #pragma unroll
            for (int ks = 0; ks < 2; ks++) {
                int k0 = ks * 16;
                uint32_t ah[2][4], al[2][4];
                #pragma unroll
                for (int mt = 0; mt < 2; mt++) {
                    uint32_t ra = stg + (mw + mt * 16 + ln15) * 80 + (k0 + l16) * 2;
                    ldsm4(ah[mt], ra + QSA_HI);
                    ldsm4(al[mt], ra + QSA_LO);
                }
                #pragma unroll
                for (int nt = 0; nt < 4; nt++) {
                    uint32_t rb = stg + (nw + nt * 16 + ln15) * 80 + (k0 + l16) * 2;
                    uint32_t bh[4], bl[4];
                    ldsm4(bh, rb + QSB_HI);
                    ldsm4(bl, rb + QSB_LO);
                    mma_bf16(c[0][2 * nt],     ah[0], bh[0], bh[2]);
                    mma_bf16(c[1][2 * nt],     ah[1], bh[0], bh[2]);
                    mma_bf16(c[0][2 * nt + 1], ah[0], bh[1], bh[3]);
                    mma_bf16(c[1][2 * nt + 1], ah[1], bh[1], bh[3]);
                    mma_bf16(c[0][2 * nt],     ah[0], bl[0], bl[2]);
                    mma_bf16(c[1][2 * nt],     ah[1], bl[0], bl[2]);
                    mma_bf16(c[0][2 * nt + 1], ah[0], bl[1], bl[3]);
                    mma_bf16(c[1][2 * nt + 1], ah[1], bl[1], bl[3]);
                    mma_bf16(c[0][2 * nt],     al[0], bh[0], bh[2]);
                    mma_bf16(c[1][2 * nt],     al[1], bh[0], bh[2]);
                    mma_bf16(c[0][2 * nt + 1], al[0], bh[1], bh[3]);
                    mma_bf16(c[1][2 * nt + 1], al[1], bh[1], bh[3]);
                }
            }
            __syncthreads();
            if (kc + 3 < 8) Q_LOAD(kc % 3, kc + 3);
        }

        #pragma unroll
        for (int mt = 0; mt < 2; mt++) {
            int m = m0 + mw + mt * 16 + grp;
            #pragma unroll
            for (int nt = 0; nt < 8; nt++) {
                int n = nw + nt * 8 + qid * 2;
                float b0 = bias[n], b1 = bias[n + 1];
                float v00 = c[mt][nt][0] + b0, v01 = c[mt][nt][1] + b1;
                float v10 = c[mt][nt][2] + b0, v11 = c[mt][nt][3] + b1;
                *(float2*)(g_Qp + (size_t)m * D_ + n)       = make_float2(v00, v01);
                *(float2*)(g_Qp + (size_t)(m + 8) * D_ + n) = make_float2(v10, v11);
                g_Qhi[(size_t)m * 128 + n / 2]       = pack_bf16(v00 * 0.0625f, v01 * 0.0625f);
                g_Qhi[(size_t)(m + 8) * 128 + n / 2] = pack_bf16(v10 * 0.0625f, v11 * 0.0625f);
            }
        }
        #undef Q_LOAD
    }
}

// ---------------- kernel 2: single-pass bf16 flash attention, no-max softmax ----------------
#define A_Q 0
#define A_STG 5120
#define STG_SZ (2 * 128 * 80)
#define A_K 0
#define A_V (128 * 80)
#define ASMEM_TOTAL (A_STG + 2 * STG_SZ)  // 46080

__global__ __launch_bounds__(128, 4) void attn_mma_kernel() {
    extern __shared__ char smem[];
    uint32_t sb = smem_u32(smem);
    int s = blockIdx.x, h = blockIdx.y;
    int tid = threadIdx.x, wid = tid >> 5, lane = tid & 31;
    int grp = lane >> 2, qid = lane & 3;
    int ln15 = lane & 15, l16 = (lane >> 4) * 8;

    size_t kvrow0 = (size_t)s * K_;
    int hofs = h * 16;

    {
        int r2 = tid >> 1, hf = tid & 1;
        const uint32_t* qh = g_Qhi + ((size_t)(s * Q_ + r2) * 128 + hofs + hf * 8);
        uint32_t qd = sb + r2 * 80 + hf * 32;
        CP16(qd + A_Q, qh);
        CP16(qd + A_Q + 16, qh + 4);
    }
    #pragma unroll
    for (int pc = 0; pc < 2; pc++) {
        const uint32_t* kh = g_Khi + ((kvrow0 + pc * 128 + tid) * 128 + hofs);
        const uint32_t* vv = g_Vhi + ((kvrow0 + pc * 128 + tid) * 128 + hofs);
        uint32_t db = sb + A_STG + pc * STG_SZ + tid * 80;
        #pragma unroll
        for (int i = 0; i < 4; i++) {
            CP16(db + A_K + i * 16, kh + i * 4);
            CP16(db + A_V + i * 16, vv + i * 4);
        }
        CP_COMMIT();
    }

    float o[4][4];
    #pragma unroll
    for (int nt = 0; nt < 4; nt++)
        #pragma unroll
        for (int i = 0; i < 4; i++) o[nt][i] = 0.f;
    float l0 = 0.f, l1 = 0.f;
    uint32_t qf[2][4];

    for (int c = 0; c < 4; c++) {
        if (c < 3) { CP_WAIT1(); } else { CP_WAIT0(); }
        __syncthreads();
        uint32_t stg = sb + A_STG + (c & 1) * STG_SZ;

        if (c == 0) {
            #pragma unroll
            for (int ks = 0; ks < 2; ks++) {
                uint32_t ra = sb + A_Q + (wid * 16 + ln15) * 80 + (ks * 16 + l16) * 2;
                ldsm4(qf[ks], ra);
            }
        }

        float sc[16][4];
        #pragma unroll
        for (int nt = 0; nt < 16; nt++)
            #pragma unroll
            for (int i = 0; i < 4; i++) sc[nt][i] = 0.f;
        #pragma unroll
        for (int ks = 0; ks < 2; ks++) {
            int k0 = ks * 16;
            #pragma unroll
            for (int ng = 0; ng < 8; ng++) {
                uint32_t rb = stg + A_K + (ng * 16 + ln15) * 80 + (k0 + l16) * 2;
                uint32_t bh[4];
                ldsm4(bh, rb);
                mma_bf16(sc[2 * ng],     qf[ks], bh[0], bh[2]);
                mma_bf16(sc[2 * ng + 1], qf[ks], bh[1], bh[3]);
            }
        }

        float ps0 = 0.f, ps1 = 0.f;
        #pragma unroll
        for (int nt = 0; nt < 16; nt++) {
            sc[nt][0] = __expf(sc[nt][0]);
            sc[nt][1] = __expf(sc[nt][1]);
            sc[nt][2] = __expf(sc[nt][2]);
            sc[nt][3] = __expf(sc[nt][3]);
            ps0 += sc[nt][0] + sc[nt][1];
            ps1 += sc[nt][2] + sc[nt][3];
        }
        l0 += ps0;
        l1 += ps1;

        #pragma unroll
        for (int j = 0; j < 8; j++) {
            uint32_t a[4];
            a[0] = pack_bf16(sc[2 * j][0],     sc[2 * j][1]);
            a[1] = pack_bf16(sc[2 * j][2],     sc[2 * j][3]);
            a[2] = pack_bf16(sc[2 * j + 1][0], sc[2 * j + 1][1]);
            a[3] = pack_bf16(sc[2 * j + 1][2], sc[2 * j + 1][3]);
            uint32_t va[4], vb[4];
            uint32_t rv = stg + A_V + (16 * j + ln15) * 80;
            ldsm4t(va, rv + l16 * 2);
            ldsm4t(vb, rv + (16 + l16) * 2);
            mma_bf16(o[0], a, va[0], va[1]);
            mma_bf16(o[1], a, va[2], va[3]);
            mma_bf16(o[2], a, vb[0], vb[1]);
            mma_bf16(o[3], a, vb[2], vb[3]);
        }

        __syncthreads();
        if (c < 2) {
            int pc = c + 2;
            const uint32_t* kh = g_Khi + ((kvrow0 + pc * 128 + tid) * 128 + hofs);
            const uint32_t* vv = g_Vhi + ((kvrow0 + pc * 128 + tid) * 128 + hofs);
            uint32_t db = sb + A_STG + (c & 1) * STG_SZ + tid * 80;
            #pragma unroll
            for (int i = 0; i < 4; i++) {
                CP16(db + A_K + i * 16, kh + i * 4);
                CP16(db + A_V + i * 16, vv + i * 4);
            }
            CP_COMMIT();
        }
    }

    l0 += __shfl_xor_sync(0xffffffffu, l0, 1);
    l0 += __shfl_xor_sync(0xffffffffu, l0, 2);
    l1 += __shfl_xor_sync(0xffffffffu, l1, 1);
    l1 += __shfl_xor_sync(0xffffffffu, l1, 2);
    float inv0 = 1.0f / l0, inv1 = 1.0f / l1;

    size_t row0 = (size_t)s * Q_ + wid * 16 + grp;
    #pragma unroll
    for (int nt = 0; nt < 4; nt++) {
        int col = h * DH_ + nt * 8 + qid * 2;
        float2 q0 = *(const float2*)(g_Qp + row0 * D_ + col);
        float2 q1 = *(const float2*)(g_Qp + (row0 + 8) * D_ + col);
        float2 r0 = make_float2(q0.x + o[nt][0] * inv0, q0.y + o[nt][1] * inv0);
        float2 r1 = make_float2(q1.x + o[nt][2] * inv1, q1.y + o[nt][3] * inv1);
        *(float2*)(g_O + row0 * D_ + col)       = r0;
        *(float2*)(g_O + (row0 + 8) * D_ + col) = r1;
    }
}

// ---------------- kernel 3: LN1 -> FFN(mma, 3-pass) -> LN2 -> scatter; 2 seqs/CTA ----------------
// Ts laid out conflict-free: row stride 272 floats, 4 groups of 68 (bank +4 per group)
#define TSO(row, col) ((row) * 272 + ((col) >> 6) * 68 + ((col) & 63))
#define P_TS  0
#define P_AH  69632                    // 64 * 272 * 4
#define P_AL  (P_AH + 64 * 528)
#define P_BH  (P_AL + 64 * 528)
#define P_BL  (P_BH + 256 * 80)
#define POST_SMEM (P_BL + 256 * 80)    // 178176

__global__ __launch_bounds__(256, 1) void post_kernel(
                            const int* __restrict__ add_ids,
                            const float* __restrict__ g1, const float* __restrict__ b1,
                            const float* __restrict__ bl,
                            const float* __restrict__ g2, const float* __restrict__ b2,
                            float* __restrict__ d_out) {
    extern __shared__ char smemc[];
    uint32_t sbase = smem_u32(smemc);
    float* Tsf = (float*)smemc;

    int tid = threadIdx.x;
    int wid = tid >> 5, lane = tid & 31;
    int grp = lane >> 2, qid = lane & 3;
    int ln15 = lane & 15, l16 = (lane >> 4) * 8;
    int row = tid >> 2, g = tid & 3;
    int d0 = g * 64;
    int n0w = wid * 32;

    const uint32_t* blH = (const uint32_t*)g_Whi[3] + (size_t)tid * 128;
    const uint32_t* blL = (const uint32_t*)g_Wlo[3] + (size_t)tid * 128;
    uint32_t bdst = sbase + tid * 80;

    for (int ss = 0; ss < 2; ss++) {
        int s = blockIdx.x * 2 + ss;
        if (ss == 1) __syncthreads();

        // ---- load + LN1 ----
        const float* Ob = g_O + ((size_t)s * Q_ + row) * D_;
        float sum = 0.f, sq = 0.f;
        float vbuf[64];
        #pragma unroll
        for (int i = 0; i < 16; i++) {
            float4 v = *(const float4*)(Ob + d0 + 4 * i);
            *(float4*)&vbuf[4 * i] = v;
            sum += v.x + v.y + v.z + v.w;
            sq  += v.x * v.x + v.y * v.y + v.z * v.z + v.w * v.w;
        }
        sum += __shfl_xor_sync(0xffffffffu, sum, 1); sum += __shfl_xor_sync(0xffffffffu, sum, 2);
        sq  += __shfl_xor_sync(0xffffffffu, sq, 1);  sq  += __shfl_xor_sync(0xffffffffu, sq, 2);
        float mu = sum * (1.0f / 256.0f);
        float var = sq * (1.0f / 256.0f) - mu * mu;
        float rstd = rsqrtf(var + EPSV);
        #pragma unroll
        for (int i = 0; i < 16; i++) {
            int d = d0 + 4 * i;
            float4 v = *(float4*)&vbuf[4 * i];
            float4 gg = *(const float4*)(g1 + d);
            float4 bb = *(const float4*)(b1 + d);
            v.x = (v.x - mu) * rstd * gg.x + bb.x;
            v.y = (v.y - mu) * rstd * gg.y + bb.y;
            v.z = (v.z - mu) * rstd * gg.z + bb.z;
            v.w = (v.w - mu) * rstd * gg.w + bb.w;
            *(float4*)&Tsf[TSO(row, d)] = v;
            uint2 hv, lv;
            split2(v.x, v.y, hv.x, lv.x);
            split2(v.z, v.w, hv.y, lv.y);
            *(uint2*)(smemc + P_AH + row * 528 + d * 2) = hv;
            *(uint2*)(smemc + P_AL + row * 528 + d * 2) = lv;
        }

        // ---- FFN: 3-pass bf16 mma ----
        float c[4][4][4];
        #pragma unroll
        for (int mt = 0; mt < 4; mt++)
            #pragma unroll
            for (int j = 0; j < 4; j++)
                #pragma unroll
                for (int i = 0; i < 4; i++) c[mt][j][i] = 0.f;

        for (int kc = 0; kc < 8; kc++) {
            __syncthreads();
            #pragma unroll
            for (int i = 0; i < 4; i++) {
                CP16(bdst + P_BH + i * 16, blH + kc * 16 + i * 4);
                CP16(bdst + P_BL + i * 16, blL + kc * 16 + i * 4);
            }
            CP_COMMIT();
            CP_WAIT0();
            __syncthreads();

            #pragma unroll
            for (int ks = 0; ks < 2; ks++) {
                int kg = kc * 32 + ks * 16;
                uint32_t ah[4][4], al[4][4];
                #pragma unroll
                for (int mt = 0; mt < 4; mt++) {
                    uint32_t ra = sbase + (mt * 16 + ln15) * 528 + (kg + l16) * 2;
                    ldsm4(ah[mt], ra + P_AH);
                    ldsm4(al[mt], ra + P_AL);
                }
                #pragma unroll
                for (int nt = 0; nt < 2; nt++) {
                    uint32_t rb = sbase + (n0w + nt * 16 + ln15) * 80 + (ks * 16 + l16) * 2;
                    uint32_t bh[4], blr[4];
                    ldsm4(bh, rb + P_BH);
                    ldsm4(blr, rb + P_BL);
                    #pragma unroll
                    for (int mt = 0; mt < 4; mt++) {
                        mma_bf16(c[mt][2 * nt],     ah[mt], bh[0], bh[2]);
                        mma_bf16(c[mt][2 * nt + 1], ah[mt], bh[1], bh[3]);
                    }
                    #pragma unroll
                    for (int mt = 0; mt < 4; mt++) {
                        mma_bf16(c[mt][2 * nt],     ah[mt], blr[0], blr[2]);
                        mma_bf16(c[mt][2 * nt + 1], ah[mt], blr[1], blr[3]);
                    }
                    #pragma unroll
                    for (int mt = 0; mt < 4; mt++) {
                        mma_bf16(c[mt][2 * nt],     al[mt], bh[0], bh[2]);
                        mma_bf16(c[mt][2 * nt + 1], al[mt], bh[1], bh[3]);
                    }
                }
            }
        }
        __syncthreads();

        // ---- residual + relu into Ts ----
        #pragma unroll
        for (int mt = 0; mt < 4; mt++) {
            int m = mt * 16 + grp;
            #pragma unroll
            for (int j = 0; j < 4; j++) {
                int n = n0w + (j >> 1) * 16 + (j & 1) * 8 + qid * 2;
                float b0 = bl[n], b1 = bl[n + 1];
                Tsf[TSO(m, n)]         += fmaxf(c[mt][j][0] + b0, 0.f);
                Tsf[TSO(m, n + 1)]     += fmaxf(c[mt][j][1] + b1, 0.f);
                Tsf[TSO(m + 8, n)]     += fmaxf(c[mt][j][2] + b0, 0.f);
                Tsf[TSO(m + 8, n + 1)] += fmaxf(c[mt][j][3] + b1, 0.f);
            }
        }
        __syncthreads();

        // ---- LN2 + scatter-add ----
        sum = 0.f; sq = 0.f;
        #pragma unroll
        for (int i = 0; i < 16; i++) {
            float4 v = *(float4*)&Tsf[TSO(row, d0 + 4 * i)];
            sum += v.x + v.y + v.z + v.w;
            sq  += v.x * v.x + v.y * v.y + v.z * v.z + v.w * v.w;
        }
        sum += __shfl_xor_sync(0xffffffffu, sum, 1); sum += __shfl_xor_sync(0xffffffffu, sum, 2);
        sq  += __shfl_xor_sync(0xffffffffu, sq, 1);  sq  += __shfl_xor_sync(0xffffffffu, sq, 2);
        mu = sum * (1.0f / 256.0f);
        var = sq * (1.0f / 256.0f) - mu * mu;
        rstd = rsqrtf(var + EPSV);

        int krow = add_ids[s * Q_ + row];
        float* outb = d_out + ((size_t)s * K_ + krow) * D_;
        #pragma unroll
        for (int i = 0; i < 16; i++) {
            int d = d0 + 4 * i;
            float4 v  = *(float4*)&Tsf[TSO(row, d)];
            float4 gg = *(const float4*)(g2 + d);
            float4 bb = *(const float4*)(b2 + d);
            float4 cur = *(const float4*)(outb + d);
            cur.x += (v.x - mu) * rstd * gg.x + bb.x;
            cur.y += (v.y - mu) * rstd * gg.y + bb.y;
            cur.z += (v.z - mu) * rstd * gg.z + bb.z;
            cur.w += (v.w - mu) * rstd * gg.w + bb.w;
            *(float4*)(outb + d) = cur;
        }
    }
}

// ---------------- launch ----------------
extern "C" void kernel_launch(void* const* d_in, const int* in_sizes, int n_in,
                              void* d_out, int out_size) {
    const float* x          = (const float*)d_in[0];
    const int*   target_ids = (const int*)  d_in[1];
    const int*   add_ids    = (const int*)  d_in[2];
    const float* Wq = (const float*)d_in[3];
    const float* bq = (const float*)d_in[4];
    const float* Wk = (const float*)d_in[5];
    const float* bk = (const float*)d_in[6];
    const float* Wv = (const float*)d_in[7];
    const float* bv = (const float*)d_in[8];
    const float* g1 = (const float*)d_in[9];
    const float* b1 = (const float*)d_in[10];
    const float* Wl = (const float*)d_in[11];
    const float* bl = (const float*)d_in[12];
    const float* g2 = (const float*)d_in[13];
    const float* b2 = (const float*)d_in[14];
    float* out = (float*)d_out;

    cudaFuncSetAttribute(gemm_all_kernel, cudaFuncAttributeMaxDynamicSharedMemorySize, PROJ_SMEM);
    cudaFuncSetAttribute(attn_mma_kernel, cudaFuncAttributeMaxDynamicSharedMemorySize, ASMEM_TOTAL);
    cudaFuncSetAttribute(post_kernel,     cudaFuncAttributeMaxDynamicSharedMemorySize, POST_SMEM);

    prep_kernel<<<256 + (S_ * Q_) / 8, 256>>>(Wk, Wv, Wq, Wl, add_ids, target_ids, x);

    gemm_all_kernel<<<4096 + (S_ * Q_) / 128, 512, PROJ_SMEM>>>(x, target_ids, bk, bv, bq, out);

    attn_mma_kernel<<<dim3(S_, H_), 128, ASMEM_TOTAL>>>();

    post_kernel<<<S_ / 2, 256, POST_SMEM>>>(add_ids, g1, b1, bl, g2, b2, out);
}

// round 17
// speedup vs baseline: 1.0246x; 1.0246x over previous
#include <cuda_runtime.h>
#include <cuda_bf16.h>
#include <math.h>
#include <stdint.h>

#define S_ 512
#define K_ 512
#define Q_ 64
#define D_ 256
#define H_ 8
#define DH_ 32
#define EPSV 1e-5f

// ---------------- scratch ----------------
__device__ float    g_Qp [(size_t)S_ * Q_ * D_];
__device__ float    g_O  [(size_t)S_ * Q_ * D_];
__device__ __nv_bfloat16 g_Whi[4][D_ * D_];             // 0=k,1=v,2=q,3=l
__device__ __nv_bfloat16 g_Wlo[4][D_ * D_];
__device__ uint32_t g_AQhi[(size_t)S_ * Q_ * (D_ / 2)];
__device__ uint32_t g_AQlo[(size_t)S_ * Q_ * (D_ / 2)];
__device__ uint32_t g_Khi[(size_t)S_ * K_ * (D_ / 2)];
__device__ uint32_t g_Vhi[(size_t)S_ * K_ * (D_ / 2)];
__device__ uint32_t g_Qhi[(size_t)S_ * Q_ * (D_ / 2)];  // bf16(Qp/16)

// ---------------- helpers ----------------
__device__ __forceinline__ uint32_t smem_u32(const void* p) {
    uint32_t a;
    asm("{ .reg .u64 t; cvta.to.shared.u64 t, %1; cvt.u32.u64 %0, t; }" : "=r"(a) : "l"(p));
    return a;
}
__device__ __forceinline__ void split2(float a, float b, uint32_t& hi, uint32_t& lo) {
    __nv_bfloat16 ah = __float2bfloat16_rn(a);
    __nv_bfloat16 bh = __float2bfloat16_rn(b);
    __nv_bfloat16 al = __float2bfloat16_rn(a - __bfloat162float(ah));
    __nv_bfloat16 bl = __float2bfloat16_rn(b - __bfloat162float(bh));
    hi = (uint32_t)*(uint16_t*)&ah | ((uint32_t)*(uint16_t*)&bh << 16);
    lo = (uint32_t)*(uint16_t*)&al | ((uint32_t)*(uint16_t*)&bl << 16);
}
__device__ __forceinline__ uint32_t pack_bf16(float a, float b) {
    __nv_bfloat162 t = __floats2bfloat162_rn(a, b);
    return *(uint32_t*)&t;
}
__device__ __forceinline__ void mma_bf16(float* c, const uint32_t* a, uint32_t b0, uint32_t b1) {
    asm volatile(
        "mma.sync.aligned.m16n8k16.row.col.f32.bf16.bf16.f32 "
        "{%0,%1,%2,%3}, {%4,%5,%6,%7}, {%8,%9}, {%0,%1,%2,%3};"
        : "+f"(c[0]), "+f"(c[1]), "+f"(c[2]), "+f"(c[3])
        : "r"(a[0]), "r"(a[1]), "r"(a[2]), "r"(a[3]), "r"(b0), "r"(b1));
}
__device__ __forceinline__ void ldsm4(uint32_t* r, uint32_t addr) {
    asm volatile("ldmatrix.sync.aligned.m8n8.x4.shared.b16 {%0,%1,%2,%3}, [%4];"
                 : "=r"(r[0]), "=r"(r[1]), "=r"(r[2]), "=r"(r[3]) : "r"(addr));
}
__device__ __forceinline__ void ldsm4t(uint32_t* r, uint32_t addr) {
    asm volatile("ldmatrix.sync.aligned.m8n8.x4.trans.shared.b16 {%0,%1,%2,%3}, [%4];"
                 : "=r"(r[0]), "=r"(r[1]), "=r"(r[2]), "=r"(r[3]) : "r"(addr));
}
#define CP16(dst, src) asm volatile("cp.async.cg.shared.global [%0], [%1], 16;" :: "r"(dst), "l"(src) : "memory")
#define CP_COMMIT()    asm volatile("cp.async.commit_group;" ::: "memory")
#define CP_WAIT0()     asm volatile("cp.async.wait_group 0;" ::: "memory")
#define CP_WAIT1()     asm volatile("cp.async.wait_group 1;" ::: "memory")
#define CP_WAIT2()     asm volatile("cp.async.wait_group 2;" ::: "memory")

// ---------------- kernel 0: merged prep (wconv + qprep) ----------------
__global__ void prep_kernel(const float* __restrict__ Wk, const float* __restrict__ Wv,
                            const float* __restrict__ Wq, const float* __restrict__ Wl,
                            const int* __restrict__ add_ids,
                            const int* __restrict__ target_ids,
                            const float* __restrict__ x) {
    int bx = blockIdx.x;
    if (bx < 256) {
        int i = bx * 256 + threadIdx.x;
        const float* src[4] = {Wk, Wv, Wq, Wl};
        #pragma unroll
        for (int w = 0; w < 4; w++) {
            float v = src[w][i];
            __nv_bfloat16 h = __float2bfloat16_rn(v);
            __nv_bfloat16 l = __float2bfloat16_rn(v - __bfloat162float(h));
            g_Whi[w][i] = h;
            g_Wlo[w][i] = l;
        }
    } else {
        int qi = (bx - 256) * 8 + (threadIdx.x >> 5);
        int lane = threadIdx.x & 31;
        int s = qi >> 6;
        int xrow = target_ids[s * K_ + add_ids[qi]];
        const float4* sp = (const float4*)(x + (size_t)xrow * D_ + lane * 8);
        float4 v0 = sp[0], v1 = sp[1];
        uint4 h, l;
        split2(v0.x, v0.y, h.x, l.x);
        split2(v0.z, v0.w, h.y, l.y);
        split2(v1.x, v1.y, h.z, l.z);
        split2(v1.z, v1.w, h.w, l.w);
        *(uint4*)(g_AQhi + (size_t)qi * 128 + lane * 4) = h;
        *(uint4*)(g_AQlo + (size_t)qi * 128 + lane * 4) = l;
    }
}

// ---------------- kernel 1: merged projection GEMM ----------------
#define KV_AF32 0u
#define KV_ABF  16384u
#define KV_B    26624u
#define KV_STAGE 47104u
#define QSA_HI 0u
#define QSA_LO 10240u
#define QSB_HI 20480u
#define QSB_LO 40960u
#define QSTAGE 61440u
#define PROJ_SMEM (3 * 61440)

__global__ __launch_bounds__(512, 1) void gemm_all_kernel(
    const float* __restrict__ x, const int* __restrict__ target_ids,
    const float* __restrict__ bk, const float* __restrict__ bv,
    const float* __restrict__ bq, float* __restrict__ d_out)
{
    extern __shared__ char smem[];
    uint32_t sb = smem_u32(smem);
    int tid = threadIdx.x, wid = tid >> 5, lane = tid & 31;
    int grp = lane >> 2, qid = lane & 3;
    int ln15 = lane & 15, l16 = (lane >> 4) * 8;
    int mw = (wid & 3) * 32, nw = (wid >> 2) * 64;
    int bx = blockIdx.x;

    if (bx < 4096) {
        int sel = bx & 1;
        int m0 = (bx >> 1) * 128;
        const float* bias = sel ? bv : bk;

        int arow = tid >> 3, apart = tid & 7;
        int rid0 = target_ids[m0 + arow];
        int rid1 = target_ids[m0 + 64 + arow];
        const float* ax0 = x + (size_t)rid0 * D_ + apart * 4;
        const float* ax1 = x + (size_t)rid1 * D_ + apart * 4;
        uint32_t adst0 = sb + KV_AF32 + (uint32_t)tid * 16;
        uint32_t adst1 = sb + KV_AF32 + (uint32_t)(tid + 512) * 16;

        int rb_row = tid >> 1, rb_h = tid & 1;
        const uint32_t* bH = (const uint32_t*)g_Whi[sel] + (size_t)rb_row * 128 + rb_h * 8;
        uint32_t bdst = sb + KV_B + rb_row * 80 + rb_h * 32;

        int crow = tid >> 2, cq = tid & 3;
        bool wr_out = (sel == 0);

        #define KV_LOAD(slot, kc) do { \
            uint32_t so = (uint32_t)(slot) * KV_STAGE; \
            CP16(adst0 + so, ax0 + (kc) * 32); \
            CP16(adst1 + so, ax1 + (kc) * 32); \
            CP16(bdst + so, bH + (kc) * 16); \
            CP16(bdst + so + 16, bH + (kc) * 16 + 4); \
            CP_COMMIT(); \
        } while (0)

        float c[2][8][4];
        #pragma unroll
        for (int mt = 0; mt < 2; mt++)
            #pragma unroll
            for (int nt = 0; nt < 8; nt++)
                #pragma unroll
                for (int i = 0; i < 4; i++) c[mt][nt][i] = 0.f;

        KV_LOAD(0, 0);
        KV_LOAD(1, 1);
        KV_LOAD(2, 2);

        for (int kc = 0; kc < 8; kc++) {
            if (kc < 6) { CP_WAIT2(); } else if (kc == 6) { CP_WAIT1(); } else { CP_WAIT0(); }
            __syncthreads();
            uint32_t so = (uint32_t)(kc % 3) * KV_STAGE;
            char* stgc = smem + so;

            {
                const float4* fsrc = (const float4*)(stgc + KV_AF32 + crow * 128 + cq * 32);
                float4 a0 = fsrc[0], a1 = fsrc[1];
                uint4 hv;
                hv.x = pack_bf16(a0.x, a0.y);
                hv.y = pack_bf16(a0.z, a0.w);
                hv.z = pack_bf16(a1.x, a1.y);
                hv.w = pack_bf16(a1.z, a1.w);
                *(uint4*)(stgc + KV_ABF + crow * 80 + cq * 16) = hv;
                if (wr_out) {
                    float4* op = (float4*)(d_out + (size_t)(m0 + crow) * D_ + kc * 32 + cq * 8);
                    op[0] = a0; op[1] = a1;
                }
            }
            __syncthreads();

            uint32_t stg = sb + so;
            #pragma unroll
            for (int ks = 0; ks < 2; ks++) {
                int k0 = ks * 16;
                uint32_t ah[2][4];
                #pragma unroll
                for (int mt = 0; mt < 2; mt++) {
                    uint32_t ra = stg + KV_ABF + (mw + mt * 16 + ln15) * 80 + (k0 + l16) * 2;
                    ldsm4(ah[mt], ra);
                }
                #pragma unroll
                for (int nt = 0; nt < 4; nt++) {
                    uint32_t rb = stg + KV_B + (nw + nt * 16 + ln15) * 80 + (k0 + l16) * 2;
                    uint32_t bh[4];
                    ldsm4(bh, rb);
                    mma_bf16(c[0][2 * nt],     ah[0], bh[0], bh[2]);
                    mma_bf16(c[1][2 * nt],     ah[1], bh[0], bh[2]);
                    mma_bf16(c[0][2 * nt + 1], ah[0], bh[1], bh[3]);
                    mma_bf16(c[1][2 * nt + 1], ah[1], bh[1], bh[3]);
                }
            }
            __syncthreads();
            if (kc + 3 < 8) KV_LOAD(kc % 3, kc + 3);
        }

        uint32_t* outp = sel ? g_Vhi : g_Khi;
        #pragma unroll
        for (int mt = 0; mt < 2; mt++) {
            int m = m0 + mw + mt * 16 + grp;
            #pragma unroll
            for (int nt = 0; nt < 8; nt++) {
                int n = nw + nt * 8 + qid * 2;
                float b0 = bias[n], b1 = bias[n + 1];
                outp[(size_t)m * 128 + n / 2]       = pack_bf16(c[mt][nt][0] + b0, c[mt][nt][1] + b1);
                outp[(size_t)(m + 8) * 128 + n / 2] = pack_bf16(c[mt][nt][2] + b0, c[mt][nt][3] + b1);
            }
        }
        #undef KV_LOAD
    } else {
        int m0 = (bx - 4096) * 128;
        const float* bias = bq;

        int ra_row = tid >> 2, ra_sg = tid & 3;
        int rb_row = tid >> 1, rb_h = (tid & 1);
        const uint32_t* aH = g_AQhi + (size_t)(m0 + ra_row) * 128 + ra_sg * 4;
        const uint32_t* aL = g_AQlo + (size_t)(m0 + ra_row) * 128 + ra_sg * 4;
        const uint32_t* bH = (const uint32_t*)g_Whi[2] + (size_t)rb_row * 128 + rb_h * 8;
        const uint32_t* bL = (const uint32_t*)g_Wlo[2] + (size_t)rb_row * 128 + rb_h * 8;
        uint32_t adst = sb + ra_row * 80 + ra_sg * 16;
        uint32_t bdst = sb + rb_row * 80 + rb_h * 32;

        #define Q_LOAD(slot, kc) do { \
            uint32_t so = (uint32_t)(slot) * QSTAGE; \
            int ko = (kc) * 16; \
            CP16(adst + so + QSA_HI, aH + ko); \
            CP16(adst + so + QSA_LO, aL + ko); \
            CP16(bdst + so + QSB_HI, bH + ko); \
            CP16(bdst + so + QSB_HI + 16, bH + ko + 4); \
            CP16(bdst + so + QSB_LO, bL + ko); \
            CP16(bdst + so + QSB_LO + 16, bL + ko + 4); \
            CP_COMMIT(); \
        } while (0)

        float c[2][8][4];
        #pragma unroll
        for (int mt = 0; mt < 2; mt++)
            #pragma unroll
            for (int nt = 0; nt < 8; nt++)
                #pragma unroll
                for (int i = 0; i < 4; i++) c[mt][nt][i] = 0.f;

        Q_LOAD(0, 0);
        Q_LOAD(1, 1);
        Q_LOAD(2, 2);

        for (int kc = 0; kc < 8; kc++) {
            if (kc < 6) { CP_WAIT2(); } else if (kc == 6) { CP_WAIT1(); } else { CP_WAIT0(); }
            __syncthreads();
            uint32_t stg = sb + (uint32_t)(kc % 3) * QSTAGE;

            #pragma unroll
            for (int ks = 0; ks < 2; ks++) {
                int k0 = ks * 16;
                uint32_t ah[2][4], al[2][4];
                #pragma unroll
                for (int mt = 0; mt < 2; mt++) {
                    uint32_t ra = stg + (mw + mt * 16 + ln15) * 80 + (k0 + l16) * 2;
                    ldsm4(ah[mt], ra + QSA_HI);
                    ldsm4(al[mt], ra + QSA_LO);
                }
                #pragma unroll
                for (int nt = 0; nt < 4; nt++) {
                    uint32_t rb = stg + (nw + nt * 16 + ln15) * 80 + (k0 + l16) * 2;
                    uint32_t bh[4], bl[4];
                    ldsm4(bh, rb + QSB_HI);
                    ldsm4(bl, rb + QSB_LO);
                    mma_bf16(c[0][2 * nt],     ah[0], bh[0], bh[2]);
                    mma_bf16(c[1][2 * nt],     ah[1], bh[0], bh[2]);
                    mma_bf16(c[0][2 * nt + 1], ah[0], bh[1], bh[3]);
                    mma_bf16(c[1][2 * nt + 1], ah[1], bh[1], bh[3]);
                    mma_bf16(c[0][2 * nt],     ah[0], bl[0], bl[2]);
                    mma_bf16(c[1][2 * nt],     ah[1], bl[0], bl[2]);
                    mma_bf16(c[0][2 * nt + 1], ah[0], bl[1], bl[3]);
                    mma_bf16(c[1][2 * nt + 1], ah[1], bl[1], bl[3]);
                    mma_bf16(c[0][2 * nt],     al[0], bh[0], bh[2]);
                    mma_bf16(c[1][2 * nt],     al[1], bh[0], bh[2]);
                    mma_bf16(c[0][2 * nt + 1], al[0], bh[1], bh[3]);
                    mma_bf16(c[1][2 * nt + 1], al[1], bh[1], bh[3]);
                }
            }
            __syncthreads();
            if (kc + 3 < 8) Q_LOAD(kc % 3, kc + 3);
        }

        #pragma unroll
        for (int mt = 0; mt < 2; mt++) {
            int m = m0 + mw + mt * 16 + grp;
            #pragma unroll
            for (int nt = 0; nt < 8; nt++) {
                int n = nw + nt * 8 + qid * 2;
                float b0 = bias[n], b1 = bias[n + 1];
                float v00 = c[mt][nt][0] + b0, v01 = c[mt][nt][1] + b1;
                float v10 = c[mt][nt][2] + b0, v11 = c[mt][nt][3] + b1;
                *(float2*)(g_Qp + (size_t)m * D_ + n)       = make_float2(v00, v01);
                *(float2*)(g_Qp + (size_t)(m + 8) * D_ + n) = make_float2(v10, v11);
                g_Qhi[(size_t)m * 128 + n / 2]       = pack_bf16(v00 * 0.0625f, v01 * 0.0625f);
                g_Qhi[(size_t)(m + 8) * 128 + n / 2] = pack_bf16(v10 * 0.0625f, v11 * 0.0625f);
            }
        }
        #undef Q_LOAD
    }
}

// ---------------- kernel 2: single-pass bf16 flash attention, no-max softmax ----------------
#define A_Q 0
#define A_STG 5120
#define STG_SZ (2 * 128 * 80)
#define A_K 0
#define A_V (128 * 80)
#define ASMEM_TOTAL (A_STG + 2 * STG_SZ)  // 46080

__global__ __launch_bounds__(128, 4) void attn_mma_kernel() {
    extern __shared__ char smem[];
    uint32_t sb = smem_u32(smem);
    int s = blockIdx.x, h = blockIdx.y;
    int tid = threadIdx.x, wid = tid >> 5, lane = tid & 31;
    int grp = lane >> 2, qid = lane & 3;
    int ln15 = lane & 15, l16 = (lane >> 4) * 8;

    size_t kvrow0 = (size_t)s * K_;
    int hofs = h * 16;

    {
        int r2 = tid >> 1, hf = tid & 1;
        const uint32_t* qh = g_Qhi + ((size_t)(s * Q_ + r2) * 128 + hofs + hf * 8);
        uint32_t qd = sb + r2 * 80 + hf * 32;
        CP16(qd + A_Q, qh);
        CP16(qd + A_Q + 16, qh + 4);
    }
    #pragma unroll
    for (int pc = 0; pc < 2; pc++) {
        const uint32_t* kh = g_Khi + ((kvrow0 + pc * 128 + tid) * 128 + hofs);
        const uint32_t* vv = g_Vhi + ((kvrow0 + pc * 128 + tid) * 128 + hofs);
        uint32_t db = sb + A_STG + pc * STG_SZ + tid * 80;
        #pragma unroll
        for (int i = 0; i < 4; i++) {
            CP16(db + A_K + i * 16, kh + i * 4);
            CP16(db + A_V + i * 16, vv + i * 4);
        }
        CP_COMMIT();
    }

    float o[4][4];
    #pragma unroll
    for (int nt = 0; nt < 4; nt++)
        #pragma unroll
        for (int i = 0; i < 4; i++) o[nt][i] = 0.f;
    float l0 = 0.f, l1 = 0.f;
    uint32_t qf[2][4];

    for (int c = 0; c < 4; c++) {
        if (c < 3) { CP_WAIT1(); } else { CP_WAIT0(); }
        __syncthreads();
        uint32_t stg = sb + A_STG + (c & 1) * STG_SZ;

        if (c == 0) {
            #pragma unroll
            for (int ks = 0; ks < 2; ks++) {
                uint32_t ra = sb + A_Q + (wid * 16 + ln15) * 80 + (ks * 16 + l16) * 2;
                ldsm4(qf[ks], ra);
            }
        }

        float sc[16][4];
        #pragma unroll
        for (int nt = 0; nt < 16; nt++)
            #pragma unroll
            for (int i = 0; i < 4; i++) sc[nt][i] = 0.f;
        #pragma unroll
        for (int ks = 0; ks < 2; ks++) {
            int k0 = ks * 16;
            #pragma unroll
            for (int ng = 0; ng < 8; ng++) {
                uint32_t rb = stg + A_K + (ng * 16 + ln15) * 80 + (k0 + l16) * 2;
                uint32_t bh[4];
                ldsm4(bh, rb);
                mma_bf16(sc[2 * ng],     qf[ks], bh[0], bh[2]);
                mma_bf16(sc[2 * ng + 1], qf[ks], bh[1], bh[3]);
            }
        }

        float ps0 = 0.f, ps1 = 0.f;
        #pragma unroll
        for (int nt = 0; nt < 16; nt++) {
            sc[nt][0] = __expf(sc[nt][0]);
            sc[nt][1] = __expf(sc[nt][1]);
            sc[nt][2] = __expf(sc[nt][2]);
            sc[nt][3] = __expf(sc[nt][3]);
            ps0 += sc[nt][0] + sc[nt][1];
            ps1 += sc[nt][2] + sc[nt][3];
        }
        l0 += ps0;
        l1 += ps1;

        #pragma unroll
        for (int j = 0; j < 8; j++) {
            uint32_t a[4];
            a[0] = pack_bf16(sc[2 * j][0],     sc[2 * j][1]);
            a[1] = pack_bf16(sc[2 * j][2],     sc[2 * j][3]);
            a[2] = pack_bf16(sc[2 * j + 1][0], sc[2 * j + 1][1]);
            a[3] = pack_bf16(sc[2 * j + 1][2], sc[2 * j + 1][3]);
            uint32_t va[4], vb[4];
            uint32_t rv = stg + A_V + (16 * j + ln15) * 80;
            ldsm4t(va, rv + l16 * 2);
            ldsm4t(vb, rv + (16 + l16) * 2);
            mma_bf16(o[0], a, va[0], va[1]);
            mma_bf16(o[1], a, va[2], va[3]);
            mma_bf16(o[2], a, vb[0], vb[1]);
            mma_bf16(o[3], a, vb[2], vb[3]);
        }

        __syncthreads();
        if (c < 2) {
            int pc = c + 2;
            const uint32_t* kh = g_Khi + ((kvrow0 + pc * 128 + tid) * 128 + hofs);
            const uint32_t* vv = g_Vhi + ((kvrow0 + pc * 128 + tid) * 128 + hofs);
            uint32_t db = sb + A_STG + (c & 1) * STG_SZ + tid * 80;
            #pragma unroll
            for (int i = 0; i < 4; i++) {
                CP16(db + A_K + i * 16, kh + i * 4);
                CP16(db + A_V + i * 16, vv + i * 4);
            }
            CP_COMMIT();
        }
    }

    l0 += __shfl_xor_sync(0xffffffffu, l0, 1);
    l0 += __shfl_xor_sync(0xffffffffu, l0, 2);
    l1 += __shfl_xor_sync(0xffffffffu, l1, 1);
    l1 += __shfl_xor_sync(0xffffffffu, l1, 2);
    float inv0 = 1.0f / l0, inv1 = 1.0f / l1;

    size_t row0 = (size_t)s * Q_ + wid * 16 + grp;
    #pragma unroll
    for (int nt = 0; nt < 4; nt++) {
        int col = h * DH_ + nt * 8 + qid * 2;
        float2 q0 = *(const float2*)(g_Qp + row0 * D_ + col);
        float2 q1 = *(const float2*)(g_Qp + (row0 + 8) * D_ + col);
        float2 r0 = make_float2(q0.x + o[nt][0] * inv0, q0.y + o[nt][1] * inv0);
        float2 r1 = make_float2(q1.x + o[nt][2] * inv1, q1.y + o[nt][3] * inv1);
        *(float2*)(g_O + row0 * D_ + col)       = r0;
        *(float2*)(g_O + (row0 + 8) * D_ + col) = r1;
    }
}

// ---------------- kernel 3: LN1 -> FFN(mma, 2-pass: ah*bh + ah*bl) -> LN2 -> scatter; 2 seqs/CTA ----------------
#define P_TS  0
#define P_AH  66560                     // 64 x 260 floats
#define P_BH  (P_AH + 64 * 528)         // 100352
#define P_BL  (P_BH + 256 * 80)         // 120832
#define POST_SMEM (P_BL + 256 * 80)     // 141312

__global__ __launch_bounds__(256, 1) void post_kernel(
                            const int* __restrict__ add_ids,
                            const float* __restrict__ g1, const float* __restrict__ b1,
                            const float* __restrict__ bl,
                            const float* __restrict__ g2, const float* __restrict__ b2,
                            float* __restrict__ d_out) {
    extern __shared__ char smemc[];
    uint32_t sbase = smem_u32(smemc);
    float (*Ts)[260] = (float(*)[260])smemc;

    int tid = threadIdx.x;
    int wid = tid >> 5, lane = tid & 31;
    int grp = lane >> 2, qid = lane & 3;
    int ln15 = lane & 15, l16 = (lane >> 4) * 8;
    int row = tid >> 2, g = tid & 3;
    int d0 = g * 64;
    int n0w = wid * 32;

    const uint32_t* blH = (const uint32_t*)g_Whi[3] + (size_t)tid * 128;
    const uint32_t* blL = (const uint32_t*)g_Wlo[3] + (size_t)tid * 128;
    uint32_t bdst = sbase + tid * 80;

    for (int ss = 0; ss < 2; ss++) {
        int s = blockIdx.x * 2 + ss;
        if (ss == 1) __syncthreads();  // previous sequence's smem fully consumed

        // ---- load + LN1, write fp32 to Ts and bf16-hi to A tile ----
        const float* Ob = g_O + ((size_t)s * Q_ + row) * D_;
        float sum = 0.f, sq = 0.f;
        float vbuf[64];
        #pragma unroll
        for (int i = 0; i < 16; i++) {
            float4 v = *(const float4*)(Ob + d0 + 4 * i);
            *(float4*)&vbuf[4 * i] = v;
            sum += v.x + v.y + v.z + v.w;
            sq  += v.x * v.x + v.y * v.y + v.z * v.z + v.w * v.w;
        }
        sum += __shfl_xor_sync(0xffffffffu, sum, 1); sum += __shfl_xor_sync(0xffffffffu, sum, 2);
        sq  += __shfl_xor_sync(0xffffffffu, sq, 1);  sq  += __shfl_xor_sync(0xffffffffu, sq, 2);
        float mu = sum * (1.0f / 256.0f);
        float var = sq * (1.0f / 256.0f) - mu * mu;
        float rstd = rsqrtf(var + EPSV);
        #pragma unroll
        for (int i = 0; i < 16; i++) {
            int d = d0 + 4 * i;
            float4 v = *(float4*)&vbuf[4 * i];
            float4 gg = *(const float4*)(g1 + d);
            float4 bb = *(const float4*)(b1 + d);
            v.x = (v.x - mu) * rstd * gg.x + bb.x;
            v.y = (v.y - mu) * rstd * gg.y + bb.y;
            v.z = (v.z - mu) * rstd * gg.z + bb.z;
            v.w = (v.w - mu) * rstd * gg.w + bb.w;
            *(float4*)&Ts[row][d] = v;
            uint2 hv;
            hv.x = pack_bf16(v.x, v.y);
            hv.y = pack_bf16(v.z, v.w);
            *(uint2*)(smemc + P_AH + row * 528 + d * 2) = hv;
        }

        // ---- FFN: y = LN1 @ Wl.T via 2-pass bf16 mma (ah*bh + ah*bl) ----
        float c[4][4][4];
        #pragma unroll
        for (int mt = 0; mt < 4; mt++)
            #pragma unroll
            for (int j = 0; j < 4; j++)
                #pragma unroll
                for (int i = 0; i < 4; i++) c[mt][j][i] = 0.f;

        for (int kc = 0; kc < 8; kc++) {
            __syncthreads();
            #pragma unroll
            for (int i = 0; i < 4; i++) {
                CP16(bdst + P_BH + i * 16, blH + kc * 16 + i * 4);
                CP16(bdst + P_BL + i * 16, blL + kc * 16 + i * 4);
            }
            CP_COMMIT();
            CP_WAIT0();
            __syncthreads();

            #pragma unroll
            for (int ks = 0; ks < 2; ks++) {
                int kg = kc * 32 + ks * 16;
                uint32_t ah[4][4];
                #pragma unroll
                for (int mt = 0; mt < 4; mt++) {
                    uint32_t ra = sbase + (mt * 16 + ln15) * 528 + (kg + l16) * 2;
                    ldsm4(ah[mt], ra + P_AH);
                }
                #pragma unroll
                for (int nt = 0; nt < 2; nt++) {
                    uint32_t rb = sbase + (n0w + nt * 16 + ln15) * 80 + (ks * 16 + l16) * 2;
                    uint32_t bh[4], blr[4];
                    ldsm4(bh, rb + P_BH);
                    ldsm4(blr, rb + P_BL);
                    #pragma unroll
                    for (int mt = 0; mt < 4; mt++) {
                        mma_bf16(c[mt][2 * nt],     ah[mt], bh[0], bh[2]);
                        mma_bf16(c[mt][2 * nt + 1], ah[mt], bh[1], bh[3]);
                    }
                    #pragma unroll
                    for (int mt = 0; mt < 4; mt++) {
                        mma_bf16(c[mt][2 * nt],     ah[mt], blr[0], blr[2]);
                        mma_bf16(c[mt][2 * nt + 1], ah[mt], blr[1], blr[3]);
                    }
                }
            }
        }
        __syncthreads();

        // ---- residual + relu into Ts ----
        #pragma unroll
        for (int mt = 0; mt < 4; mt++) {
            int m = mt * 16 + grp;
            #pragma unroll
            for (int j = 0; j < 4; j++) {
                int n = n0w + (j >> 1) * 16 + (j & 1) * 8 + qid * 2;
                float b0 = bl[n], b1 = bl[n + 1];
                Ts[m][n]     += fmaxf(c[mt][j][0] + b0, 0.f);
                Ts[m][n + 1] += fmaxf(c[mt][j][1] + b1, 0.f);
                Ts[m + 8][n]     += fmaxf(c[mt][j][2] + b0, 0.f);
                Ts[m + 8][n + 1] += fmaxf(c[mt][j][3] + b1, 0.f);
            }
        }
        __syncthreads();

        // ---- LN2 + scatter-add ----
        sum = 0.f; sq = 0.f;
        #pragma unroll
        for (int i = 0; i < 16; i++) {
            float4 v = *(float4*)&Ts[row][d0 + 4 * i];
            sum += v.x + v.y + v.z + v.w;
            sq  += v.x * v.x + v.y * v.y + v.z * v.z + v.w * v.w;
        }
        sum += __shfl_xor_sync(0xffffffffu, sum, 1); sum += __shfl_xor_sync(0xffffffffu, sum, 2);
        sq  += __shfl_xor_sync(0xffffffffu, sq, 1);  sq  += __shfl_xor_sync(0xffffffffu, sq, 2);
        mu = sum * (1.0f / 256.0f);
        var = sq * (1.0f / 256.0f) - mu * mu;
        rstd = rsqrtf(var + EPSV);

        int krow = add_ids[s * Q_ + row];
        float* outb = d_out + ((size_t)s * K_ + krow) * D_;
        #pragma unroll
        for (int i = 0; i < 16; i++) {
            int d = d0 + 4 * i;
            float4 v  = *(float4*)&Ts[row][d];
            float4 gg = *(const float4*)(g2 + d);
            float4 bb = *(const float4*)(b2 + d);
            float4 cur = *(const float4*)(outb + d);
            cur.x += (v.x - mu) * rstd * gg.x + bb.x;
            cur.y += (v.y - mu) * rstd * gg.y + bb.y;
            cur.z += (v.z - mu) * rstd * gg.z + bb.z;
            cur.w += (v.w - mu) * rstd * gg.w + bb.w;
            *(float4*)(outb + d) = cur;
        }
    }
}

// ---------------- launch ----------------
extern "C" void kernel_launch(void* const* d_in, const int* in_sizes, int n_in,
                              void* d_out, int out_size) {
    const float* x          = (const float*)d_in[0];
    const int*   target_ids = (const int*)  d_in[1];
    const int*   add_ids    = (const int*)  d_in[2];
    const float* Wq = (const float*)d_in[3];
    const float* bq = (const float*)d_in[4];
    const float* Wk = (const float*)d_in[5];
    const float* bk = (const float*)d_in[6];
    const float* Wv = (const float*)d_in[7];
    const float* bv = (const float*)d_in[8];
    const float* g1 = (const float*)d_in[9];
    const float* b1 = (const float*)d_in[10];
    const float* Wl = (const float*)d_in[11];
    const float* bl = (const float*)d_in[12];
    const float* g2 = (const float*)d_in[13];
    const float* b2 = (const float*)d_in[14];
    float* out = (float*)d_out;

    cudaFuncSetAttribute(gemm_all_kernel, cudaFuncAttributeMaxDynamicSharedMemorySize, PROJ_SMEM);
    cudaFuncSetAttribute(attn_mma_kernel, cudaFuncAttributeMaxDynamicSharedMemorySize, ASMEM_TOTAL);
    cudaFuncSetAttribute(post_kernel,     cudaFuncAttributeMaxDynamicSharedMemorySize, POST_SMEM);

    prep_kernel<<<256 + (S_ * Q_) / 8, 256>>>(Wk, Wv, Wq, Wl, add_ids, target_ids, x);

    gemm_all_kernel<<<4096 + (S_ * Q_) / 128, 512, PROJ_SMEM>>>(x, target_ids, bk, bv, bq, out);

    attn_mma_kernel<<<dim3(S_, H_), 128, ASMEM_TOTAL>>>();

    post_kernel<<<S_ / 2, 256, POST_SMEM>>>(add_ids, g1, b1, bl, g2, b2, out);
}